// round 3
// baseline (speedup 1.0000x reference)
#include <cuda_runtime.h>
#include <cstdint>

// Problem constants
#define T_DIM 2048
#define B_DIM 4
#define C_DIM 1024
#define H_DIM 16
#define K_TAPS 15
#define M_DIM (T_DIM * B_DIM)     // 8192 rows (t*B + b)
#define N_DIM (H_DIM * K_TAPS)    // 240 logits per row
#define KD    C_DIM               // 1024 reduction dim

// Scratch: softmaxed dynamic weights (T*B, 240) fp32; pre-rounded tf32 Wlin
__device__ float    g_w[M_DIM * N_DIM];
__device__ uint32_t g_bw[N_DIM * KD];

__device__ __forceinline__ uint32_t f2tf(float f) {
    uint32_t u;
    asm("cvt.rna.tf32.f32 %0, %1;" : "=r"(u) : "f"(f));
    return u;
}

// ---------------- Prologue: Wlin -> tf32(rna) bits, once ----------------
extern "C" __global__ void __launch_bounds__(256)
cvt_b_kernel(const float* __restrict__ W) {
    int i = blockIdx.x * 256 + threadIdx.x;      // 61440 float4 total
    float4 v = ((const float4*)W)[i];
    uint4 o;
    o.x = f2tf(v.x); o.y = f2tf(v.y); o.z = f2tf(v.z); o.w = f2tf(v.w);
    ((uint4*)g_bw)[i] = o;
}

// ---------------- GEMM (tf32 mma, cp.async 3-stage) + fused softmax -----
// 640 threads = 20 warps: 4 M-warps x 5 N-warps; each warp: m16 x 48 cols.
#define NTHR 640
#define BM   64
#define BK   32
#define NT   (KD / BK)            // 32 k-tiles
#define AST  36                   // padded stride (words)
#define BST  36
#define A_STAGE (BM * AST)        // 2304 words
#define B_STAGE (N_DIM * BST)     // 8640 words
#define STAGE_W (A_STAGE + B_STAGE)
#define NSTAGE  3
#define GEMM_SMEM_BYTES (NSTAGE * STAGE_W * 4)   // 131328 B
#define CST 242
#define NTW 6                     // n8-tiles per warp

extern "C" __global__ void __launch_bounds__(NTHR, 1)
gemm_softmax_kernel(const float* __restrict__ x) {
    extern __shared__ uint32_t sm[];
    const int tid  = threadIdx.x;
    const int wid  = tid >> 5;
    const int lane = tid & 31;
    const int m0   = blockIdx.x * BM;

    const int wm    = wid & 3;        // 4 M-warps
    const int wn    = wid >> 2;       // 5 N-warp groups
    const int mbase = wm * 16;
    const int nbase = wn * (NTW * 8); // 48 cols per warp
    const int lg    = lane >> 2;
    const int lk    = lane & 3;

    auto issue_tile = [&](int kb, int s) {
        uint32_t* As = sm + s * STAGE_W;
        uint32_t* Bs = As + A_STAGE;
        // A tile: 64 x 32 = 512 float4 (raw f32 bits; HW truncates to tf32)
        if (tid < 512) {
            int m = tid >> 3, kq = tid & 7;
            const float* src = x + (size_t)(m0 + m) * KD + kb + kq * 4;
            uint32_t dst = (uint32_t)__cvta_generic_to_shared(As + m * AST + kq * 4);
            asm volatile("cp.async.cg.shared.global [%0], [%1], 16;\n"
                         :: "r"(dst), "l"(src));
        }
        // B tile: 240 x 32 = 1920 float4 = 3 * 640 (pre-rounded tf32)
        #pragma unroll
        for (int it = 0; it < 3; it++) {
            int idx = it * NTHR + tid;
            int n = idx >> 3, kq = idx & 7;
            const uint32_t* src = g_bw + (size_t)n * KD + kb + kq * 4;
            uint32_t dst = (uint32_t)__cvta_generic_to_shared(Bs + n * BST + kq * 4);
            asm volatile("cp.async.cg.shared.global [%0], [%1], 16;\n"
                         :: "r"(dst), "l"(src));
        }
        asm volatile("cp.async.commit_group;\n");
    };

    float acc[NTW][4];
    #pragma unroll
    for (int i = 0; i < NTW; i++)
        #pragma unroll
        for (int j = 0; j < 4; j++) acc[i][j] = 0.f;

    // Prologue: prefetch 2 tiles
    issue_tile(0, 0);
    issue_tile(BK, 1);

    for (int kbi = 0; kbi < NT; kbi++) {
        const int s_cur = kbi % NSTAGE;
        if (kbi + 2 < NT) issue_tile((kbi + 2) * BK, (kbi + 2) % NSTAGE);

        if (kbi < NT - 2)       asm volatile("cp.async.wait_group %0;\n" :: "n"(2));
        else if (kbi == NT - 2) asm volatile("cp.async.wait_group %0;\n" :: "n"(1));
        else                    asm volatile("cp.async.wait_group %0;\n" :: "n"(0));
        __syncthreads();

        const uint32_t* As = sm + s_cur * STAGE_W;
        const uint32_t* Bs = As + A_STAGE;

        #pragma unroll
        for (int kk = 0; kk < BK; kk += 8) {
            uint32_t a0 = As[(mbase     + lg) * AST + kk     + lk];
            uint32_t a1 = As[(mbase + 8 + lg) * AST + kk     + lk];
            uint32_t a2 = As[(mbase     + lg) * AST + kk + 4 + lk];
            uint32_t a3 = As[(mbase + 8 + lg) * AST + kk + 4 + lk];
            #pragma unroll
            for (int nt = 0; nt < NTW; nt++) {
                uint32_t b0 = Bs[(nbase + nt * 8 + lg) * BST + kk     + lk];
                uint32_t b1 = Bs[(nbase + nt * 8 + lg) * BST + kk + 4 + lk];
                asm volatile(
                    "mma.sync.aligned.m16n8k8.row.col.f32.tf32.tf32.f32 "
                    "{%0,%1,%2,%3}, {%4,%5,%6,%7}, {%8,%9}, {%0,%1,%2,%3};\n"
                    : "+f"(acc[nt][0]), "+f"(acc[nt][1]),
                      "+f"(acc[nt][2]), "+f"(acc[nt][3])
                    : "r"(a0), "r"(a1), "r"(a2), "r"(a3), "r"(b0), "r"(b1));
            }
        }
        __syncthreads();   // stage s_cur is overwritten by issue at kbi+1
    }

    // ---- Epilogue: stage C in smem, softmax over K=15 per head ----
    float* Cs = (float*)sm;   // 64 x 242 floats, reuses stage buffers
    #pragma unroll
    for (int nt = 0; nt < NTW; nt++) {
        int col = nbase + nt * 8 + 2 * lk;
        Cs[(mbase     + lg) * CST + col    ] = acc[nt][0];
        Cs[(mbase     + lg) * CST + col + 1] = acc[nt][1];
        Cs[(mbase + 8 + lg) * CST + col    ] = acc[nt][2];
        Cs[(mbase + 8 + lg) * CST + col + 1] = acc[nt][3];
    }
    __syncthreads();

    for (int task = tid; task < BM * H_DIM; task += NTHR) {
        int row = task >> 4, h = task & 15;
        const float* p = Cs + row * CST + h * K_TAPS;
        float mx = p[0];
        #pragma unroll
        for (int k = 1; k < K_TAPS; k++) mx = fmaxf(mx, p[k]);
        float e[K_TAPS];
        float s = 0.f;
        #pragma unroll
        for (int k = 0; k < K_TAPS; k++) { e[k] = __expf(p[k] - mx); s += e[k]; }
        float r = 1.0f / s;
        float* o = g_w + (size_t)(m0 + row) * N_DIM + h * K_TAPS;
        #pragma unroll
        for (int k = 0; k < K_TAPS; k++) o[k] = e[k] * r;
    }
}

// ---------------- Dynamic depthwise conv (causal, K=15) ----------------
// out[t,b,c] = sum_k w[t,b,h(c),k] * x[t+k-14, b, c]
// float2 per thread -> ~60 regs -> 4 blocks/SM; one head per warp (LDS bcast)
#define TT 32   // time steps per block

extern "C" __global__ void __launch_bounds__(256, 4)
dynconv_kernel(const float* __restrict__ x, float* __restrict__ out) {
    __shared__ float ws[TT * N_DIM];   // weights for this time tile: 30 KB

    const int tid = threadIdx.x;
    const int t0  = blockIdx.x * TT;
    const int b   = blockIdx.y;
    const int c2  = blockIdx.z * 256 + tid;   // float2 channel group, 0..511
    const int h   = c2 >> 5;                  // 32 float2 per head

    const float2* x2 = (const float2*)x;
    float2*       o2 = (float2*)out;

    // Register window loads first: 15 independent LDGs in flight
    float2 win[K_TAPS];
    #pragma unroll
    for (int i = 0; i < K_TAPS; i++) {
        int t = t0 - 14 + i;
        win[i] = (t < 0) ? make_float2(0.f, 0.f)
                         : x2[(size_t)(t * B_DIM + b) * (C_DIM / 2) + c2];
    }

    // Weight tile fill overlaps the window loads
    const float4* gw4 = (const float4*)g_w;
    #pragma unroll
    for (int it = 0; it < 8; it++) {
        int idx = it * 256 + tid;            // 0..1919 float4
        if (idx < TT * (N_DIM / 4)) {
            int tt = idx / (N_DIM / 4), q = idx % (N_DIM / 4);
            ((float4*)ws)[tt * (N_DIM / 4) + q] =
                gw4[(size_t)((t0 + tt) * B_DIM + b) * (N_DIM / 4) + q];
        }
    }
    __syncthreads();

    #pragma unroll
    for (int tt = 0; tt < TT; tt++) {
        float2 nxt;
        if (tt + 1 < TT)
            nxt = x2[(size_t)((t0 + tt + 1) * B_DIM + b) * (C_DIM / 2) + c2];

        const float* wr = ws + tt * N_DIM + h * K_TAPS;
        float2 a = make_float2(0.f, 0.f);
        #pragma unroll
        for (int k = 0; k < K_TAPS; k++) {
            const float w = wr[k];
            const float2 xv = win[(tt + k) % K_TAPS];
            a.x += w * xv.x; a.y += w * xv.y;
        }
        o2[(size_t)((t0 + tt) * B_DIM + b) * (C_DIM / 2) + c2] = a;
        if (tt + 1 < TT) win[tt % K_TAPS] = nxt;
    }
}

extern "C" void kernel_launch(void* const* d_in, const int* in_sizes, int n_in,
                              void* d_out, int out_size) {
    const float* x    = (const float*)d_in[0];   // (T, B, C) f32
    const float* Wlin = (const float*)d_in[1];   // (240, 1024) f32
    float* out = (float*)d_out;                  // (T, B, C) f32

    cudaFuncSetAttribute(gemm_softmax_kernel,
                         cudaFuncAttributeMaxDynamicSharedMemorySize,
                         GEMM_SMEM_BYTES);

    cvt_b_kernel<<<N_DIM, 256>>>(Wlin);                          // 61440 float4
    gemm_softmax_kernel<<<M_DIM / BM, NTHR, GEMM_SMEM_BYTES>>>(x);
    dynconv_kernel<<<dim3(T_DIM / TT, B_DIM, 2), 256>>>(x, out);
}

// round 5
// speedup vs baseline: 1.2488x; 1.2488x over previous
#include <cuda_runtime.h>
#include <cstdint>

// Problem constants
#define T_DIM 2048
#define B_DIM 4
#define C_DIM 1024
#define H_DIM 16
#define K_TAPS 15
#define M_DIM (T_DIM * B_DIM)     // 8192 rows (t*B + b)
#define N_DIM (H_DIM * K_TAPS)    // 240 logits per row
#define KD    C_DIM               // 1024 reduction dim

// Scratch: softmaxed dynamic weights (T*B, 240) fp32; pre-rounded tf32 Wlin
__device__ float    g_w[M_DIM * N_DIM];
__device__ uint32_t g_bw[N_DIM * KD];

__device__ __forceinline__ uint32_t f2tf(float f) {
    uint32_t u;
    asm("cvt.rna.tf32.f32 %0, %1;" : "=r"(u) : "f"(f));
    return u;
}

// ---------------- Prologue: Wlin -> tf32(rna) bits, once ----------------
// 61440 float4; 60 blocks x 256 thr x 4 each (MLP=4, latency-hidden)
extern "C" __global__ void __launch_bounds__(256)
cvt_b_kernel(const float* __restrict__ W) {
    int base = blockIdx.x * 256 + threadIdx.x;
    #pragma unroll
    for (int k = 0; k < 4; k++) {
        int i = base + k * 15360;
        float4 v = ((const float4*)W)[i];
        uint4 o;
        o.x = f2tf(v.x); o.y = f2tf(v.y); o.z = f2tf(v.z); o.w = f2tf(v.w);
        ((uint4*)g_bw)[i] = o;
    }
}

// ============ GEMM (tf32 mma.sync, split-K in block) + softmax ===========
// Block: BM=64 rows, N padded to 256 cols, 512 threads = 16 warps:
//   kg (k-split, 2 groups of 8 warps) x ng (8 N-groups of 32 cols).
// Each warp: m64 x n32 tile = 16 MMAs/kk-step, acc 64 regs.
// Each kg group double-buffers its own (A,B) k-tiles; named barriers.
#define NTHR   512
#define BM     64
#define BN_PAD 256
#define BK     32
#define KHALF  (KD / 2)           // 512 per k-group
#define NT_KG  (KHALF / BK)       // 16 tiles per k-group
#define AST    36                 // padded strides (words)
#define BST    36
#define A_STG  (BM * AST)         // 2304 words
#define B_STG  (BN_PAD * BST)     // 9216 words
#define STG_W  (A_STG + B_STG)    // 11520 words = 46080 B
#define GEMM_SMEM (4 * STG_W * 4) // 184320 B (4 stages: 2 per k-group)
#define CST    242

extern "C" __global__ void __launch_bounds__(NTHR, 1)
gemm_softmax_kernel(const float* __restrict__ x) {
    extern __shared__ uint32_t sm[];
    const int tid  = threadIdx.x;
    const int wid  = tid >> 5;
    const int lane = tid & 31;
    const int m0   = blockIdx.x * BM;

    const int kg   = wid >> 3;          // k-split group 0/1
    const int ng   = wid & 7;           // N-group: cols [ng*32, ng*32+32)
    const int gtid = tid & 255;         // thread id within k-group
    const int lg   = lane >> 2;
    const int lk   = lane & 3;
    const int kofs = kg * KHALF;

    // Issue cp.async loads of one BK-tile into stage st (group-collective)
    auto issue_tile = [&](int kb, int st) {
        uint32_t* As = sm + st * STG_W;
        uint32_t* Bs = As + A_STG;
        // A: 64 rows x 32 k = 512 float4, 2 per thread
        #pragma unroll
        for (int i = 0; i < 2; i++) {
            int idx = i * 256 + gtid;
            int m = idx >> 3, kq = idx & 7;
            const float* src = x + (size_t)(m0 + m) * KD + kb + kq * 4;
            uint32_t dst = (uint32_t)__cvta_generic_to_shared(As + m * AST + kq * 4);
            asm volatile("cp.async.cg.shared.global [%0], [%1], 16;\n"
                         :: "r"(dst), "l"(src));
        }
        // B: 256 rows x 32 k = 2048 float4, 8 per thread; rows >=240 zero-fill
        #pragma unroll
        for (int i = 0; i < 8; i++) {
            int idx = i * 256 + gtid;
            int n = idx >> 3, kq = idx & 7;
            int nn = (n < N_DIM) ? n : 0;
            unsigned bytes = (n < N_DIM) ? 16u : 0u;
            const uint32_t* src = g_bw + (size_t)nn * KD + kb + kq * 4;
            uint32_t dst = (uint32_t)__cvta_generic_to_shared(Bs + n * BST + kq * 4);
            asm volatile("cp.async.cg.shared.global [%0], [%1], 16, %2;\n"
                         :: "r"(dst), "l"(src), "r"(bytes));
        }
        asm volatile("cp.async.commit_group;\n");
    };

    float acc[4][4][4];   // [m-tile][n-tile][frag]
    #pragma unroll
    for (int a = 0; a < 4; a++)
        #pragma unroll
        for (int b = 0; b < 4; b++)
            #pragma unroll
            for (int c = 0; c < 4; c++) acc[a][b][c] = 0.f;

    // Prologue: prefetch tiles 0 and 1 of this k-group
    issue_tile(kofs, kg * 2);
    issue_tile(kofs + BK, kg * 2 + 1);

    const int baridx = 1 + kg;   // named barrier per k-group (256 threads)

    for (int j = 0; j < NT_KG; j++) {
        const int st = kg * 2 + (j & 1);
        if (j == NT_KG - 1) asm volatile("cp.async.wait_group 0;\n");
        else                asm volatile("cp.async.wait_group 1;\n");
        asm volatile("bar.sync %0, 256;" :: "r"(baridx) : "memory");

        const uint32_t* As = sm + st * STG_W;
        const uint32_t* Bs = As + A_STG;

        #pragma unroll
        for (int kk = 0; kk < BK; kk += 8) {
            uint32_t a0[4], a1[4], a2[4], a3[4];
            #pragma unroll
            for (int mt = 0; mt < 4; mt++) {
                a0[mt] = As[(mt * 16     + lg) * AST + kk     + lk];
                a1[mt] = As[(mt * 16 + 8 + lg) * AST + kk     + lk];
                a2[mt] = As[(mt * 16     + lg) * AST + kk + 4 + lk];
                a3[mt] = As[(mt * 16 + 8 + lg) * AST + kk + 4 + lk];
            }
            #pragma unroll
            for (int nt = 0; nt < 4; nt++) {
                const int col = ng * 32 + nt * 8;
                uint32_t b0 = Bs[(col + lg) * BST + kk     + lk];
                uint32_t b1 = Bs[(col + lg) * BST + kk + 4 + lk];
                #pragma unroll
                for (int mt = 0; mt < 4; mt++) {
                    asm volatile(
                        "mma.sync.aligned.m16n8k8.row.col.f32.tf32.tf32.f32 "
                        "{%0,%1,%2,%3}, {%4,%5,%6,%7}, {%8,%9}, {%0,%1,%2,%3};\n"
                        : "+f"(acc[mt][nt][0]), "+f"(acc[mt][nt][1]),
                          "+f"(acc[mt][nt][2]), "+f"(acc[mt][nt][3])
                        : "r"(a0[mt]), "r"(a1[mt]), "r"(a2[mt]), "r"(a3[mt]),
                          "r"(b0), "r"(b1));
                }
            }
        }
        asm volatile("bar.sync %0, 256;" :: "r"(baridx) : "memory");
        if (j + 2 < NT_KG) issue_tile(kofs + (j + 2) * BK, st);
    }

    // ---- Split-K reduction + softmax (block-wide) ----
    __syncthreads();                 // all stages dead; reuse smem as Cs
    float* Cs = (float*)sm;          // [64][242]

    // kg1 stores its partial sums
    if (kg == 1) {
        #pragma unroll
        for (int mt = 0; mt < 4; mt++)
            #pragma unroll
            for (int nt = 0; nt < 4; nt++) {
                int col = ng * 32 + nt * 8 + 2 * lk;
                if (col < N_DIM) {
                    int row = mt * 16 + lg;
                    Cs[row * CST + col    ]       = acc[mt][nt][0];
                    Cs[row * CST + col + 1]       = acc[mt][nt][1];
                    Cs[(row + 8) * CST + col    ] = acc[mt][nt][2];
                    Cs[(row + 8) * CST + col + 1] = acc[mt][nt][3];
                }
            }
    }
    __syncthreads();
    // kg0 adds its partials on top
    if (kg == 0) {
        #pragma unroll
        for (int mt = 0; mt < 4; mt++)
            #pragma unroll
            for (int nt = 0; nt < 4; nt++) {
                int col = ng * 32 + nt * 8 + 2 * lk;
                if (col < N_DIM) {
                    int row = mt * 16 + lg;
                    Cs[row * CST + col    ]       += acc[mt][nt][0];
                    Cs[row * CST + col + 1]       += acc[mt][nt][1];
                    Cs[(row + 8) * CST + col    ] += acc[mt][nt][2];
                    Cs[(row + 8) * CST + col + 1] += acc[mt][nt][3];
                }
            }
    }
    __syncthreads();

    // Softmax over K=15 per (row, head): 64*16 = 1024 tasks
    #pragma unroll
    for (int it = 0; it < 2; it++) {
        int task = it * NTHR + tid;
        int row = task >> 4, h = task & 15;
        const float* p = Cs + row * CST + h * K_TAPS;
        float mx = p[0];
        #pragma unroll
        for (int k = 1; k < K_TAPS; k++) mx = fmaxf(mx, p[k]);
        float e[K_TAPS];
        float s = 0.f;
        #pragma unroll
        for (int k = 0; k < K_TAPS; k++) { e[k] = __expf(p[k] - mx); s += e[k]; }
        float r = 1.0f / s;
        float* o = g_w + (size_t)(m0 + row) * N_DIM + h * K_TAPS;
        #pragma unroll
        for (int k = 0; k < K_TAPS; k++) o[k] = e[k] * r;
    }
}

// ---------------- Dynamic depthwise conv (causal, K=15) ----------------
// out[t,b,c] = sum_k w[t,b,h(c),k] * x[t+k-14, b, c]
#define TT 32   // time steps per block

extern "C" __global__ void __launch_bounds__(256, 2)
dynconv_kernel(const float* __restrict__ x, float* __restrict__ out) {
    __shared__ float ws[TT * N_DIM];   // 30 KB

    const int tid = threadIdx.x;
    const int t0  = blockIdx.x * TT;
    const int b   = blockIdx.y;

    const int c4 = tid;           // float4 channel group (c = 4*tid)
    const int h  = tid >> 4;      // head

    const float4* x4 = (const float4*)x;
    float4*       o4 = (float4*)out;

    // Register window loads first: 15 independent LDGs in flight
    float4 win[K_TAPS];
    #pragma unroll
    for (int i = 0; i < K_TAPS; i++) {
        int t = t0 - 14 + i;
        win[i] = (t < 0) ? make_float4(0.f, 0.f, 0.f, 0.f)
                         : x4[(size_t)(t * B_DIM + b) * (C_DIM / 4) + c4];
    }

    const float4* gw4 = (const float4*)g_w;
    #pragma unroll
    for (int it = 0; it < 8; it++) {
        int idx = it * 256 + tid;
        if (idx < TT * (N_DIM / 4)) {
            int tt = idx / (N_DIM / 4), q = idx % (N_DIM / 4);
            ((float4*)ws)[tt * (N_DIM / 4) + q] =
                gw4[(size_t)((t0 + tt) * B_DIM + b) * (N_DIM / 4) + q];
        }
    }
    __syncthreads();

    #pragma unroll
    for (int tt = 0; tt < TT; tt++) {
        float4 nxt;
        if (tt + 1 < TT)
            nxt = x4[(size_t)((t0 + tt + 1) * B_DIM + b) * (C_DIM / 4) + c4];

        const float* wr = ws + tt * N_DIM + h * K_TAPS;
        float4 a = make_float4(0.f, 0.f, 0.f, 0.f);
        #pragma unroll
        for (int k = 0; k < K_TAPS; k++) {
            const float w = wr[k];
            const float4 xv = win[(tt + k) % K_TAPS];
            a.x += w * xv.x; a.y += w * xv.y;
            a.z += w * xv.z; a.w += w * xv.w;
        }
        o4[(size_t)((t0 + tt) * B_DIM + b) * (C_DIM / 4) + c4] = a;
        if (tt + 1 < TT) win[tt % K_TAPS] = nxt;
    }
}

extern "C" void kernel_launch(void* const* d_in, const int* in_sizes, int n_in,
                              void* d_out, int out_size) {
    const float* x    = (const float*)d_in[0];   // (T, B, C) f32
    const float* Wlin = (const float*)d_in[1];   // (240, 1024) f32
    float* out = (float*)d_out;                  // (T, B, C) f32

    cudaFuncSetAttribute(gemm_softmax_kernel,
                         cudaFuncAttributeMaxDynamicSharedMemorySize,
                         GEMM_SMEM);

    cvt_b_kernel<<<60, 256>>>(Wlin);
    gemm_softmax_kernel<<<M_DIM / BM, NTHR, GEMM_SMEM>>>(x);
    dynconv_kernel<<<dim3(T_DIM / TT, B_DIM), 256>>>(x, out);
}